// round 2
// baseline (speedup 1.0000x reference)
#include <cuda_runtime.h>
#include <cstdint>

#define D_MODEL 1024
#define FF_DIM  1024
#define BATCH   8
#define SEQ     2048
#define MTOT    (BATCH * SEQ)          // 16384
#define ATTN_SCALE 0.03125f

// ---------------------------------------------------------------------------
// Scratch (device globals: allocation-free, harness-rule compliant)
// ---------------------------------------------------------------------------
__device__ float g_Q[MTOT * FF_DIM];                   // 64 MiB
__device__ float g_K[MTOT * FF_DIM];                   // 64 MiB
__device__ float g_V[MTOT * FF_DIM];                   // 64 MiB
__device__ float g_S[(size_t)BATCH * SEQ * SEQ];       // 128 MiB

// ---------------------------------------------------------------------------
// Helpers
// ---------------------------------------------------------------------------
__device__ __forceinline__ float tf32r(float x) {
    uint32_t u;
    asm("cvt.rna.tf32.f32 %0, %1;" : "=r"(u) : "f"(x));
    return __uint_as_float(u);
}

__device__ __forceinline__ void mma8(float* c, const uint32_t* a, const uint32_t* b) {
    asm volatile(
        "mma.sync.aligned.m16n8k8.row.col.f32.tf32.tf32.f32 "
        "{%0,%1,%2,%3}, {%4,%5,%6,%7}, {%8,%9}, {%0,%1,%2,%3};\n"
        : "+f"(c[0]), "+f"(c[1]), "+f"(c[2]), "+f"(c[3])
        : "r"(a[0]), "r"(a[1]), "r"(a[2]), "r"(a[3]), "r"(b[0]), "r"(b[1]));
}

// ---------------------------------------------------------------------------
// TF32 GEMM:  C[M,N] = A[M,K] * B + bias, optional scale, optional tf32-round
//   BT=true  : B is [N,K] row-major (i.e. C = A * B^T)   -- proj, QK^T
//   BT=false : B is [K,N] row-major (i.e. C = A * B)     -- PV
// lda = K, ldb = (BT ? K : N), ldc = N. All dims divisible by tile sizes.
// ---------------------------------------------------------------------------
constexpr int BM = 128, BN = 128, BK = 32;

template <bool BT>
__global__ void __launch_bounds__(256)
gemm_tf32(const float* __restrict__ A, const float* __restrict__ B,
          const float* __restrict__ bias, float* __restrict__ C,
          int M, int N, int K,
          long long sA, long long sB, long long sC,
          float scale, int round_out)
{
    constexpr int AS_LD = BK + 4;                  // stride 36: bank=(4m+k)%32, conflict-free
    constexpr int BS_R  = BT ? BN : BK;
    constexpr int BS_LD = BT ? (BK + 4) : (BN + 8); // NN stride 136: bank=(8k+n)%32, conflict-free

    __shared__ float As[BM][AS_LD];
    __shared__ float Bs[BS_R][BS_LD];

    A += (long long)blockIdx.z * sA;
    B += (long long)blockIdx.z * sB;
    C += (long long)blockIdx.z * sC;

    const int tid  = threadIdx.x;
    const int lane = tid & 31;
    const int warp = tid >> 5;
    const int wm   = (warp & 1) * 64;   // warp row offset within tile
    const int wn   = (warp >> 1) * 32;  // warp col offset within tile
    const int gid  = lane >> 2;
    const int tig  = lane & 3;

    const int m0 = blockIdx.y * BM;
    const int n0 = blockIdx.x * BN;
    const int ldb = BT ? K : N;

    float acc[4][4][4];
    #pragma unroll
    for (int i = 0; i < 4; i++)
        #pragma unroll
        for (int j = 0; j < 4; j++)
            #pragma unroll
            for (int l = 0; l < 4; l++) acc[i][j][l] = 0.f;

    float4 ra[4], rb[4];

    auto loadA = [&](int kt) {
        #pragma unroll
        for (int i = 0; i < 4; i++) {
            int id = tid + i * 256;
            int r  = id >> 3;
            int kk = (id & 7) * 4;
            ra[i] = *(const float4*)(A + (long long)(m0 + r) * K + kt * BK + kk);
        }
    };
    auto loadB = [&](int kt) {
        if (BT) {
            #pragma unroll
            for (int i = 0; i < 4; i++) {
                int id = tid + i * 256;
                int r  = id >> 3;
                int kk = (id & 7) * 4;
                rb[i] = *(const float4*)(B + (long long)(n0 + r) * ldb + kt * BK + kk);
            }
        } else {
            #pragma unroll
            for (int i = 0; i < 4; i++) {
                int id = tid + i * 256;
                int r  = id >> 5;           // k row 0..31
                int cc = (id & 31) * 4;     // n col
                rb[i] = *(const float4*)(B + (long long)(kt * BK + r) * ldb + n0 + cc);
            }
        }
    };
    auto stsAB = [&]() {
        #pragma unroll
        for (int i = 0; i < 4; i++) {
            int id = tid + i * 256;
            int r  = id >> 3;
            int kk = (id & 7) * 4;
            float4 v = ra[i];
            v.x = tf32r(v.x); v.y = tf32r(v.y); v.z = tf32r(v.z); v.w = tf32r(v.w);
            *(float4*)&As[r][kk] = v;
        }
        if (BT) {
            #pragma unroll
            for (int i = 0; i < 4; i++) {
                int id = tid + i * 256;
                int r  = id >> 3;
                int kk = (id & 7) * 4;
                float4 v = rb[i];
                v.x = tf32r(v.x); v.y = tf32r(v.y); v.z = tf32r(v.z); v.w = tf32r(v.w);
                *(float4*)&Bs[r][kk] = v;
            }
        } else {
            #pragma unroll
            for (int i = 0; i < 4; i++) {
                int id = tid + i * 256;
                int r  = id >> 5;
                int cc = (id & 31) * 4;
                float4 v = rb[i];
                v.x = tf32r(v.x); v.y = tf32r(v.y); v.z = tf32r(v.z); v.w = tf32r(v.w);
                *(float4*)&Bs[r][cc] = v;
            }
        }
    };

    const int NK = K / BK;
    loadA(0); loadB(0);

    for (int kt = 0; kt < NK; kt++) {
        stsAB();
        __syncthreads();
        if (kt + 1 < NK) { loadA(kt + 1); loadB(kt + 1); }  // LDGs in flight during compute

        #pragma unroll
        for (int ks = 0; ks < 4; ks++) {
            const int k0 = ks * 8;
            uint32_t af[4][4];
            uint32_t bf[4][2];
            #pragma unroll
            for (int mi = 0; mi < 4; mi++) {
                int r = wm + mi * 16 + gid;
                af[mi][0] = __float_as_uint(As[r    ][k0 + tig]);
                af[mi][1] = __float_as_uint(As[r + 8][k0 + tig]);
                af[mi][2] = __float_as_uint(As[r    ][k0 + tig + 4]);
                af[mi][3] = __float_as_uint(As[r + 8][k0 + tig + 4]);
            }
            #pragma unroll
            for (int ni = 0; ni < 4; ni++) {
                int c = wn + ni * 8 + gid;
                if (BT) {
                    bf[ni][0] = __float_as_uint(Bs[c][k0 + tig]);
                    bf[ni][1] = __float_as_uint(Bs[c][k0 + tig + 4]);
                } else {
                    bf[ni][0] = __float_as_uint(Bs[k0 + tig    ][c]);
                    bf[ni][1] = __float_as_uint(Bs[k0 + tig + 4][c]);
                }
            }
            #pragma unroll
            for (int mi = 0; mi < 4; mi++)
                #pragma unroll
                for (int ni = 0; ni < 4; ni++)
                    mma8(acc[mi][ni], af[mi], bf[ni]);
        }
        __syncthreads();
    }

    // Epilogue: bias + scale + optional tf32 rounding, float2 stores
    #pragma unroll
    for (int mi = 0; mi < 4; mi++) {
        #pragma unroll
        for (int ni = 0; ni < 4; ni++) {
            int r = m0 + wm + mi * 16 + gid;
            int c = n0 + wn + ni * 8 + tig * 2;
            float b0 = 0.f, b1 = 0.f;
            if (bias) { b0 = bias[c]; b1 = bias[c + 1]; }
            float v0 = (acc[mi][ni][0] + b0) * scale;
            float v1 = (acc[mi][ni][1] + b1) * scale;
            float v2 = (acc[mi][ni][2] + b0) * scale;
            float v3 = (acc[mi][ni][3] + b1) * scale;
            if (round_out) { v0 = tf32r(v0); v1 = tf32r(v1); v2 = tf32r(v2); v3 = tf32r(v3); }
            *(float2*)(C + (long long)r * N + c)       = make_float2(v0, v1);
            *(float2*)(C + (long long)(r + 8) * N + c) = make_float2(v2, v3);
        }
    }
}

// ---------------------------------------------------------------------------
// Row softmax over 2048 columns; output rounded to tf32 (feeds PV GEMM).
// One block (256 threads) per row; each thread owns 8 elements (2x float4).
// ---------------------------------------------------------------------------
__global__ void __launch_bounds__(256)
softmax_tf32(float* __restrict__ S)
{
    __shared__ float red[8];
    float* row = S + (long long)blockIdx.x * SEQ;
    const int tid = threadIdx.x;

    float4 a = ((float4*)row)[tid];
    float4 b = ((float4*)row)[tid + 256];

    float m = fmaxf(fmaxf(fmaxf(a.x, a.y), fmaxf(a.z, a.w)),
                    fmaxf(fmaxf(b.x, b.y), fmaxf(b.z, b.w)));
    #pragma unroll
    for (int o = 16; o > 0; o >>= 1) m = fmaxf(m, __shfl_xor_sync(0xffffffffu, m, o));
    if ((tid & 31) == 0) red[tid >> 5] = m;
    __syncthreads();
    m = red[0];
    #pragma unroll
    for (int i = 1; i < 8; i++) m = fmaxf(m, red[i]);
    __syncthreads();

    a.x = __expf(a.x - m); a.y = __expf(a.y - m); a.z = __expf(a.z - m); a.w = __expf(a.w - m);
    b.x = __expf(b.x - m); b.y = __expf(b.y - m); b.z = __expf(b.z - m); b.w = __expf(b.w - m);
    float s = a.x + a.y + a.z + a.w + b.x + b.y + b.z + b.w;
    #pragma unroll
    for (int o = 16; o > 0; o >>= 1) s += __shfl_xor_sync(0xffffffffu, s, o);
    if ((tid & 31) == 0) red[tid >> 5] = s;
    __syncthreads();
    s = red[0] + red[1] + red[2] + red[3] + red[4] + red[5] + red[6] + red[7];
    const float inv = 1.0f / s;

    a.x = tf32r(a.x * inv); a.y = tf32r(a.y * inv); a.z = tf32r(a.z * inv); a.w = tf32r(a.w * inv);
    b.x = tf32r(b.x * inv); b.y = tf32r(b.y * inv); b.z = tf32r(b.z * inv); b.w = tf32r(b.w * inv);
    ((float4*)row)[tid]       = a;
    ((float4*)row)[tid + 256] = b;
}

// ---------------------------------------------------------------------------
// kernel_launch: 6 graph-capturable launches, no allocations, no syncs.
// Inputs: 0=sequence [8,2048,1024], 1=Wq [1024,1024], 2=bq, 3=Wk, 4=bk, 5=Wv, 6=bv
// Output: [8,2048,1024] fp32
// ---------------------------------------------------------------------------
extern "C" void kernel_launch(void* const* d_in, const int* in_sizes, int n_in,
                              void* d_out, int out_size)
{
    const float* seq = (const float*)d_in[0];
    const float* Wq  = (const float*)d_in[1];
    const float* bq  = (const float*)d_in[2];
    const float* Wk  = (const float*)d_in[3];
    const float* bk  = (const float*)d_in[4];
    const float* Wv  = (const float*)d_in[5];
    const float* bv  = (const float*)d_in[6];
    float* out = (float*)d_out;

    float *Qp, *Kp, *Vp, *Sp;
    cudaGetSymbolAddress((void**)&Qp, g_Q);
    cudaGetSymbolAddress((void**)&Kp, g_K);
    cudaGetSymbolAddress((void**)&Vp, g_V);
    cudaGetSymbolAddress((void**)&Sp, g_S);

    const dim3 blk(256);

    // 1-3) QKV projections: [16384,1024] = seq @ W^T + b  (SCALE folded into Q)
    const dim3 gp(FF_DIM / BN, MTOT / BM, 1);  // (8, 128)
    gemm_tf32<true><<<gp, blk>>>(seq, Wq, bq, Qp, MTOT, FF_DIM, D_MODEL, 0, 0, 0, ATTN_SCALE, 1);
    gemm_tf32<true><<<gp, blk>>>(seq, Wk, bk, Kp, MTOT, FF_DIM, D_MODEL, 0, 0, 0, 1.0f, 1);
    gemm_tf32<true><<<gp, blk>>>(seq, Wv, bv, Vp, MTOT, FF_DIM, D_MODEL, 0, 0, 0, 1.0f, 1);

    // 4) scores: per batch [2048,2048] = Q @ K^T
    const long long sQK = (long long)SEQ * FF_DIM;       // 2048*1024
    const long long sS  = (long long)SEQ * SEQ;          // 2048*2048
    const dim3 gs(SEQ / BN, SEQ / BM, BATCH);            // (16, 16, 8)
    gemm_tf32<true><<<gs, blk>>>(Qp, Kp, nullptr, Sp, SEQ, SEQ, FF_DIM, sQK, sQK, sS, 1.0f, 0);

    // 5) softmax rows (16384 rows of 2048)
    softmax_tf32<<<MTOT, blk>>>(Sp);

    // 6) output: per batch [2048,1024] = P @ V
    const dim3 go(FF_DIM / BN, SEQ / BM, BATCH);         // (8, 16, 8)
    gemm_tf32<false><<<go, blk>>>(Sp, Vp, nullptr, out, SEQ, FF_DIM, SEQ, sS, sQK, sQK, 1.0f, 0);
}

// round 5
// speedup vs baseline: 1.4547x; 1.4547x over previous
#include <cuda_runtime.h>
#include <cstdint>

#define D_MODEL 1024
#define FF      1024
#define NB      8
#define SEQ     2048
#define MTOT    (NB * SEQ)            // 16384
#define ATTN_SCALE 0.03125f

// ---------------------------------------------------------------------------
// Scratch (device globals: allocation-free)
// ---------------------------------------------------------------------------
__device__ float g_SR[(size_t)MTOT * D_MODEL];       // 64 MiB  seq, tf32-rounded
__device__ float g_WR[(size_t)3 * FF * D_MODEL];     // 12 MiB  Wq/Wk/Wv rounded
__device__ float g_Q [(size_t)MTOT * FF];            // 64 MiB
__device__ float g_K [(size_t)MTOT * FF];            // 64 MiB
__device__ float g_V [(size_t)MTOT * FF];            // 64 MiB
__device__ float g_S [(size_t)NB * SEQ * SEQ];       // 128 MiB

// ---------------------------------------------------------------------------
// Helpers
// ---------------------------------------------------------------------------
__device__ __forceinline__ float tf32r(float x) {
    uint32_t u; asm("cvt.rna.tf32.f32 %0, %1;" : "=r"(u) : "f"(x));
    return __uint_as_float(u);
}
__device__ __forceinline__ uint32_t smem_u32(const void* p) {
    uint32_t a;
    asm("{ .reg .u64 t; cvta.to.shared.u64 t, %1; cvt.u32.u64 %0, t; }" : "=r"(a) : "l"(p));
    return a;
}
__device__ __forceinline__ void cp16(uint32_t dst, const void* src) {
    asm volatile("cp.async.cg.shared.global [%0], [%1], 16;" :: "r"(dst), "l"(src) : "memory");
}
__device__ __forceinline__ void cp_commit() { asm volatile("cp.async.commit_group;" ::: "memory"); }
__device__ __forceinline__ void cp_wait1()  { asm volatile("cp.async.wait_group 1;" ::: "memory"); }
__device__ __forceinline__ uint32_t lds32(uint32_t a) {
    uint32_t v; asm("ld.shared.b32 %0, [%1];" : "=r"(v) : "r"(a));
    return v;
}
__device__ __forceinline__ void mma8(float* c, const uint32_t* a, const uint32_t* b) {
    asm volatile(
        "mma.sync.aligned.m16n8k8.row.col.f32.tf32.tf32.f32 "
        "{%0,%1,%2,%3}, {%4,%5,%6,%7}, {%8,%9}, {%0,%1,%2,%3};\n"
        : "+f"(c[0]), "+f"(c[1]), "+f"(c[2]), "+f"(c[3])
        : "r"(a[0]), "r"(a[1]), "r"(a[2]), "r"(a[3]), "r"(b[0]), "r"(b[1]));
}

// ---------------------------------------------------------------------------
// TF32 GEMM v2: C[M,N] = A[M,K]*op(B) (+bias)*scale, optional tf32-round out.
//   BT=true : B[N,K] row-major (C = A B^T)    -- proj, QK^T
//   BT=false: B[K,N] row-major (C = A B)      -- PV
// CTA tile 128x256x32, 8 warps (warp tile 64x64), 3-stage cp.async ring.
// A (and TN B) smem: row-major 128B rows, 16B-chunk XOR swizzle (c ^= r&7).
// NN B smem: [32][264] padded rows (bank-conflict-free fragment reads).
// ---------------------------------------------------------------------------
constexpr int BM = 128, BN = 256, BK = 32, STG = 3;
constexpr int A_BY   = BM * BK * 4;          // 16384
constexpr int BNN_LD = BN + 8;               // 264 floats per NN row
constexpr int BB_BY  = BK * BNN_LD * 4;      // 33792 (>= TN's 32768)
constexpr int STGB   = A_BY + BB_BY;         // 50176
constexpr int SMEM_TOTAL = STG * STGB;       // 150528

template <bool BT>
__global__ void __launch_bounds__(256)
gemm2(const float* __restrict__ A, const float* __restrict__ B,
      const float* __restrict__ bias, float* __restrict__ C,
      int K, int ldb, int ldc,
      long long sA, long long sB, long long sC,
      float scale, int round_out)
{
    extern __shared__ char smp[];
    const uint32_t sb = smem_u32(smp);
    const int tid = threadIdx.x, lane = tid & 31, warp = tid >> 5;
    const int gid = lane >> 2, tig = lane & 3;
    const int wm = (warp & 1) * 64, wn = (warp >> 1) * 64;
    const int m0 = blockIdx.y * BM, n0 = blockIdx.x * BN;

    const float* Ab = A + (long long)blockIdx.z * sA;
    const float* Bb = B + (long long)blockIdx.z * sB;
    C += (long long)blockIdx.z * sC;

    // ---- precomputed cp.async offsets (per thread) ----
    uint32_t dA[4]; long long oA[4];
    #pragma unroll
    for (int i = 0; i < 4; i++) {
        int id = tid + i * 256, r = id >> 3, c = id & 7;
        dA[i] = (uint32_t)(r * 128 + ((c ^ (r & 7)) * 16));
        oA[i] = (long long)(m0 + r) * K + c * 4;
    }
    uint32_t dB[8]; long long oB[8];
    #pragma unroll
    for (int i = 0; i < 8; i++) {
        int id = tid + i * 256;
        if (BT) {
            int r = id >> 3, c = id & 7;
            dB[i] = (uint32_t)(r * 128 + ((c ^ (r & 7)) * 16));
            oB[i] = (long long)(n0 + r) * ldb + c * 4;
        } else {
            int kr = id >> 6, c = id & 63;
            dB[i] = (uint32_t)(kr * (BNN_LD * 4) + c * 16);
            oB[i] = (long long)kr * ldb + n0 + c * 4;
        }
    }

    auto loads = [&](int kt) {
        const uint32_t st  = sb + (kt % STG) * STGB;
        const uint32_t stb = st + A_BY;
        const float* Ak = Ab + kt * BK;
        #pragma unroll
        for (int i = 0; i < 4; i++) cp16(st + dA[i], Ak + oA[i]);
        const float* Bk = BT ? (Bb + kt * BK) : (Bb + (long long)kt * BK * ldb);
        #pragma unroll
        for (int i = 0; i < 8; i++) cp16(stb + dB[i], Bk + oB[i]);
        cp_commit();
    };

    float acc[4][8][4];
    #pragma unroll
    for (int i = 0; i < 4; i++)
        #pragma unroll
        for (int j = 0; j < 8; j++)
            #pragma unroll
            for (int l = 0; l < 4; l++) acc[i][j][l] = 0.f;

    const int NK = K / BK;
    loads(0); loads(1);

    uint32_t af[2][4][4], bf[2][8][2];

    auto lfA = [&](uint32_t st, int ks, uint32_t f[4][4]) {
        const uint32_t ch0 = ((uint32_t)(2 * ks) ^ (uint32_t)gid) * 16 + tig * 4;
        const uint32_t ch1 = ((uint32_t)(2 * ks + 1) ^ (uint32_t)gid) * 16 + tig * 4;
        #pragma unroll
        for (int mi = 0; mi < 4; mi++) {
            const uint32_t rb = st + (wm + mi * 16 + gid) * 128;
            f[mi][0] = lds32(rb + ch0);
            f[mi][1] = lds32(rb + 8 * 128 + ch0);
            f[mi][2] = lds32(rb + ch1);
            f[mi][3] = lds32(rb + 8 * 128 + ch1);
        }
    };
    auto lfB = [&](uint32_t stb, int ks, uint32_t f[8][2]) {
        if (BT) {
            const uint32_t ch0 = ((uint32_t)(2 * ks) ^ (uint32_t)gid) * 16 + tig * 4;
            const uint32_t ch1 = ((uint32_t)(2 * ks + 1) ^ (uint32_t)gid) * 16 + tig * 4;
            #pragma unroll
            for (int ni = 0; ni < 8; ni++) {
                const uint32_t rb = stb + (wn + ni * 8 + gid) * 128;
                f[ni][0] = lds32(rb + ch0);
                f[ni][1] = lds32(rb + ch1);
            }
        } else {
            const uint32_t rb = stb + (8 * ks + tig) * (BNN_LD * 4) + (wn + gid) * 4;
            #pragma unroll
            for (int ni = 0; ni < 8; ni++) {
                f[ni][0] = lds32(rb + ni * 32);
                f[ni][1] = lds32(rb + 4 * (BNN_LD * 4) + ni * 32);
            }
        }
    };

    for (int kt = 0; kt < NK; kt++) {
        cp_wait1();                       // stage kt landed
        __syncthreads();                  // visible to all; stage kt-1 fully consumed
        if (kt + 2 < NK) loads(kt + 2);   // refill stage (kt+2)%3 == (kt-1)%3
        else cp_commit();                 // keep group accounting uniform

        const uint32_t st  = sb + (kt % STG) * STGB;
        const uint32_t stb = st + A_BY;

        lfA(st, 0, af[0]); lfB(stb, 0, bf[0]);
        #pragma unroll
        for (int ks = 0; ks < 4; ks++) {
            const int cur = ks & 1, nxt = cur ^ 1;
            if (ks < 3) { lfA(st, ks + 1, af[nxt]); lfB(stb, ks + 1, bf[nxt]); }
            #pragma unroll
            for (int mi = 0; mi < 4; mi++)
                #pragma unroll
                for (int ni = 0; ni < 8; ni++)
                    mma8(acc[mi][ni], af[cur][mi], bf[cur][ni]);
        }
    }

    // ---- epilogue: bias + scale + optional tf32 round, float2 stores ----
    #pragma unroll
    for (int mi = 0; mi < 4; mi++) {
        const int r = m0 + wm + mi * 16 + gid;
        #pragma unroll
        for (int ni = 0; ni < 8; ni++) {
            const int c = n0 + wn + ni * 8 + tig * 2;
            float b0 = 0.f, b1 = 0.f;
            if (bias) { b0 = bias[c]; b1 = bias[c + 1]; }
            float v0 = (acc[mi][ni][0] + b0) * scale;
            float v1 = (acc[mi][ni][1] + b1) * scale;
            float v2 = (acc[mi][ni][2] + b0) * scale;
            float v3 = (acc[mi][ni][3] + b1) * scale;
            if (round_out) { v0 = tf32r(v0); v1 = tf32r(v1); v2 = tf32r(v2); v3 = tf32r(v3); }
            *(float2*)(C + (long long)r * ldc + c)       = make_float2(v0, v1);
            *(float2*)(C + (long long)(r + 8) * ldc + c) = make_float2(v2, v3);
        }
    }
}

// ---------------------------------------------------------------------------
// Elementwise tf32 rounding (float4 grid-stride)
// ---------------------------------------------------------------------------
__global__ void __launch_bounds__(256)
round_tf32(const float4* __restrict__ in, float4* __restrict__ out, int n4)
{
    for (int i = blockIdx.x * 256 + threadIdx.x; i < n4; i += gridDim.x * 256) {
        float4 v = in[i];
        v.x = tf32r(v.x); v.y = tf32r(v.y); v.z = tf32r(v.z); v.w = tf32r(v.w);
        out[i] = v;
    }
}

// ---------------------------------------------------------------------------
// Row softmax over 2048 cols; output tf32-rounded (feeds PV GEMM).
// ---------------------------------------------------------------------------
__global__ void __launch_bounds__(256)
softmax_tf32(float* __restrict__ S)
{
    __shared__ float red[8];
    float* row = S + (long long)blockIdx.x * SEQ;
    const int tid = threadIdx.x;

    float4 a = ((float4*)row)[tid];
    float4 b = ((float4*)row)[tid + 256];

    float m = fmaxf(fmaxf(fmaxf(a.x, a.y), fmaxf(a.z, a.w)),
                    fmaxf(fmaxf(b.x, b.y), fmaxf(b.z, b.w)));
    #pragma unroll
    for (int o = 16; o > 0; o >>= 1) m = fmaxf(m, __shfl_xor_sync(0xffffffffu, m, o));
    if ((tid & 31) == 0) red[tid >> 5] = m;
    __syncthreads();
    m = red[0];
    #pragma unroll
    for (int i = 1; i < 8; i++) m = fmaxf(m, red[i]);
    __syncthreads();

    a.x = __expf(a.x - m); a.y = __expf(a.y - m); a.z = __expf(a.z - m); a.w = __expf(a.w - m);
    b.x = __expf(b.x - m); b.y = __expf(b.y - m); b.z = __expf(b.z - m); b.w = __expf(b.w - m);
    float s = a.x + a.y + a.z + a.w + b.x + b.y + b.z + b.w;
    #pragma unroll
    for (int o = 16; o > 0; o >>= 1) s += __shfl_xor_sync(0xffffffffu, s, o);
    if ((tid & 31) == 0) red[tid >> 5] = s;
    __syncthreads();
    s = red[0] + red[1] + red[2] + red[3] + red[4] + red[5] + red[6] + red[7];
    const float inv = 1.0f / s;

    a.x = tf32r(a.x * inv); a.y = tf32r(a.y * inv); a.z = tf32r(a.z * inv); a.w = tf32r(a.w * inv);
    b.x = tf32r(b.x * inv); b.y = tf32r(b.y * inv); b.z = tf32r(b.z * inv); b.w = tf32r(b.w * inv);
    ((float4*)row)[tid]       = a;
    ((float4*)row)[tid + 256] = b;
}

// ---------------------------------------------------------------------------
// kernel_launch — graph-capturable, allocation-free.
// Inputs: 0=sequence, 1=Wq, 2=bq, 3=Wk, 4=bk, 5=Wv, 6=bv. Output fp32.
// ---------------------------------------------------------------------------
extern "C" void kernel_launch(void* const* d_in, const int* in_sizes, int n_in,
                              void* d_out, int out_size)
{
    const float* seq = (const float*)d_in[0];
    const float* Wq  = (const float*)d_in[1];
    const float* bq  = (const float*)d_in[2];
    const float* Wk  = (const float*)d_in[3];
    const float* bk  = (const float*)d_in[4];
    const float* Wv  = (const float*)d_in[5];
    const float* bv  = (const float*)d_in[6];
    float* out = (float*)d_out;

    float *SR, *WR, *Qp, *Kp, *Vp, *Sp;
    cudaGetSymbolAddress((void**)&SR, g_SR);
    cudaGetSymbolAddress((void**)&WR, g_WR);
    cudaGetSymbolAddress((void**)&Qp, g_Q);
    cudaGetSymbolAddress((void**)&Kp, g_K);
    cudaGetSymbolAddress((void**)&Vp, g_V);
    cudaGetSymbolAddress((void**)&Sp, g_S);

    cudaFuncSetAttribute(gemm2<true>,  cudaFuncAttributeMaxDynamicSharedMemorySize, SMEM_TOTAL);
    cudaFuncSetAttribute(gemm2<false>, cudaFuncAttributeMaxDynamicSharedMemorySize, SMEM_TOTAL);

    const dim3 blk(256);
    const int WSZ = FF * D_MODEL;

    // 0) pre-round inputs to tf32 (makes in-MMA conversion exact)
    round_tf32<<<2048, blk>>>((const float4*)seq, (float4*)SR, MTOT * D_MODEL / 4);
    round_tf32<<<512,  blk>>>((const float4*)Wq, (float4*)(WR + 0 * (size_t)WSZ), WSZ / 4);
    round_tf32<<<512,  blk>>>((const float4*)Wk, (float4*)(WR + 1 * (size_t)WSZ), WSZ / 4);
    round_tf32<<<512,  blk>>>((const float4*)Wv, (float4*)(WR + 2 * (size_t)WSZ), WSZ / 4);

    // 1-3) projections: [16384,1024] = SR @ W^T + b (SCALE folded into Q)
    const dim3 gp(FF / BN, MTOT / BM, 1);        // (4, 128)
    gemm2<true><<<gp, blk, SMEM_TOTAL>>>(SR, WR + 0 * (size_t)WSZ, bq, Qp,
                                         D_MODEL, D_MODEL, FF, 0, 0, 0, ATTN_SCALE, 1);
    gemm2<true><<<gp, blk, SMEM_TOTAL>>>(SR, WR + 1 * (size_t)WSZ, bk, Kp,
                                         D_MODEL, D_MODEL, FF, 0, 0, 0, 1.0f, 1);
    gemm2<true><<<gp, blk, SMEM_TOTAL>>>(SR, WR + 2 * (size_t)WSZ, bv, Vp,
                                         D_MODEL, D_MODEL, FF, 0, 0, 0, 1.0f, 1);

    // 4) scores: per batch [2048,2048] = Q @ K^T
    const long long sQK = (long long)SEQ * FF;
    const long long sS  = (long long)SEQ * SEQ;
    const dim3 gs(SEQ / BN, SEQ / BM, NB);       // (8, 16, 8)
    gemm2<true><<<gs, blk, SMEM_TOTAL>>>(Qp, Kp, nullptr, Sp,
                                         FF, FF, SEQ, sQK, sQK, sS, 1.0f, 0);

    // 5) softmax (rounds P to tf32)
    softmax_tf32<<<MTOT, blk>>>(Sp);

    // 6) output: per batch [2048,1024] = P @ V
    const dim3 go(FF / BN, SEQ / BM, NB);        // (4, 16, 8)
    gemm2<false><<<go, blk, SMEM_TOTAL>>>(Sp, Vp, nullptr, out,
                                          SEQ, FF, FF, sS, sQK, sQK, 1.0f, 0);
}

// round 6
// speedup vs baseline: 1.4742x; 1.0135x over previous
#include <cuda_runtime.h>
#include <cstdint>

#define D_MODEL 1024
#define FF      1024
#define NB      8
#define SEQ     2048
#define MTOT    (NB * SEQ)            // 16384
#define ATTN_SCALE 0.03125f

// ---------------------------------------------------------------------------
// Scratch (device globals: allocation-free)
// ---------------------------------------------------------------------------
__device__ float g_SR[(size_t)MTOT * D_MODEL];       // 64 MiB  seq, tf32-rounded
__device__ float g_WR[(size_t)3 * FF * D_MODEL];     // 12 MiB  Wq/Wk/Wv rounded
__device__ float g_Q [(size_t)MTOT * FF];            // 64 MiB
__device__ float g_K [(size_t)MTOT * FF];            // 64 MiB
__device__ float g_V [(size_t)MTOT * FF];            // 64 MiB
__device__ float g_S [(size_t)NB * SEQ * SEQ];       // 128 MiB

// ---------------------------------------------------------------------------
// Helpers
// ---------------------------------------------------------------------------
__device__ __forceinline__ float tf32r(float x) {
    uint32_t u; asm("cvt.rna.tf32.f32 %0, %1;" : "=r"(u) : "f"(x));
    return __uint_as_float(u);
}
__device__ __forceinline__ uint32_t smem_u32(const void* p) {
    uint32_t a;
    asm("{ .reg .u64 t; cvta.to.shared.u64 t, %1; cvt.u32.u64 %0, t; }" : "=r"(a) : "l"(p));
    return a;
}
__device__ __forceinline__ void cp16(uint32_t dst, const void* src) {
    asm volatile("cp.async.cg.shared.global [%0], [%1], 16;" :: "r"(dst), "l"(src) : "memory");
}
__device__ __forceinline__ void cp_commit() { asm volatile("cp.async.commit_group;" ::: "memory"); }
__device__ __forceinline__ void cp_wait1()  { asm volatile("cp.async.wait_group 1;" ::: "memory"); }
__device__ __forceinline__ uint32_t lds32(uint32_t a) {
    uint32_t v; asm("ld.shared.b32 %0, [%1];" : "=r"(v) : "r"(a));
    return v;
}
__device__ __forceinline__ void mma8(float* c, const uint32_t* a, const uint32_t* b) {
    asm volatile(
        "mma.sync.aligned.m16n8k8.row.col.f32.tf32.tf32.f32 "
        "{%0,%1,%2,%3}, {%4,%5,%6,%7}, {%8,%9}, {%0,%1,%2,%3};\n"
        : "+f"(c[0]), "+f"(c[1]), "+f"(c[2]), "+f"(c[3])
        : "r"(a[0]), "r"(a[1]), "r"(a[2]), "r"(a[3]), "r"(b[0]), "r"(b[1]));
}

// Per-z operand selection (for the fused QKV projection launch)
struct Ptrs { const float* B; const float* bias; float* C; float scale; };
struct Sel  { Ptrs p[3]; };

// ---------------------------------------------------------------------------
// TF32 GEMM v3: C[M,N] = A[M,K]*op(B) (+bias)*scale, optional tf32-round out.
//   BT=true : B[N,K] row-major (C = A B^T)    -- proj, QK^T
//   BT=false: B[K,N] row-major (C = A B)      -- PV
// CTA tile 128 x BNT x 32, 8 warps (warp grid 2x4, warp tile 64 x BNT/4),
// 3-stage cp.async ring. TN smem: 128B rows, 16B-chunk XOR swizzle.
// NN B smem: [32][BNT+8] padded rows.
// fused=1: blockIdx.z selects sel.p[z] (strides sA/sB/sC are 0 in that mode).
// ---------------------------------------------------------------------------
constexpr int BM = 128, BK = 32, STG = 3;
constexpr int A_BY = BM * BK * 4;            // 16384

template <bool BT, int BNT>
__global__ void __launch_bounds__(256)
gemm3(const float* __restrict__ A, Sel sel, int fused,
      int K, int ldb, int ldc,
      long long sA, long long sB, long long sC,
      int round_out)
{
    constexpr int NI     = BNT / 32;          // n8 blocks per warp
    constexpr int WN     = BNT / 4;           // warp n tile
    constexpr int CPR    = BNT / 4;           // NN 16B-chunks per smem row
    constexpr int BNN_LD = BNT + 8;
    constexpr int BB_BY  = BT ? BNT * 128 : BK * BNN_LD * 4;
    constexpr int STGB   = A_BY + BB_BY;

    extern __shared__ char smp[];
    const uint32_t sb = smem_u32(smp);
    const int tid = threadIdx.x, lane = tid & 31, warp = tid >> 5;
    const int gid = lane >> 2, tig = lane & 3;
    const int wm = (warp & 1) * 64, wn = (warp >> 1) * WN;
    const int m0 = blockIdx.y * BM, n0 = blockIdx.x * BNT;
    const int z  = blockIdx.z;

    const Ptrs pp = sel.p[fused ? z : 0];
    const float* Ab = A    + (long long)z * sA;
    const float* Bb = pp.B + (long long)z * sB;
    float*       Cb = pp.C + (long long)z * sC;
    const float* bias = pp.bias;
    const float  scale = pp.scale;

    // ---- precomputed cp.async offsets (per thread) ----
    uint32_t dA[4]; long long oA[4];
    #pragma unroll
    for (int i = 0; i < 4; i++) {
        int id = tid + i * 256, r = id >> 3, c = id & 7;
        dA[i] = (uint32_t)(r * 128 + ((c ^ (r & 7)) * 16));
        oA[i] = (long long)(m0 + r) * K + c * 4;
    }
    uint32_t dB[NI]; long long oB[NI];
    #pragma unroll
    for (int i = 0; i < NI; i++) {
        int id = tid + i * 256;
        if (BT) {
            int r = id >> 3, c = id & 7;
            dB[i] = (uint32_t)(r * 128 + ((c ^ (r & 7)) * 16));
            oB[i] = (long long)(n0 + r) * ldb + c * 4;
        } else {
            int kr = id / CPR, c = id % CPR;
            dB[i] = (uint32_t)(kr * (BNN_LD * 4) + c * 16);
            oB[i] = (long long)kr * ldb + n0 + c * 4;
        }
    }

    auto loads = [&](int kt) {
        const uint32_t st  = sb + (kt % STG) * STGB;
        const uint32_t stb = st + A_BY;
        const float* Ak = Ab + kt * BK;
        #pragma unroll
        for (int i = 0; i < 4; i++) cp16(st + dA[i], Ak + oA[i]);
        const float* Bk = BT ? (Bb + kt * BK) : (Bb + (long long)kt * BK * ldb);
        #pragma unroll
        for (int i = 0; i < NI; i++) cp16(stb + dB[i], Bk + oB[i]);
        cp_commit();
    };

    float acc[4][NI][4];
    #pragma unroll
    for (int i = 0; i < 4; i++)
        #pragma unroll
        for (int j = 0; j < NI; j++)
            #pragma unroll
            for (int l = 0; l < 4; l++) acc[i][j][l] = 0.f;

    const int NK = K / BK;
    loads(0); loads(1);

    uint32_t af[2][4][4], bf[2][NI][2];

    auto lfA = [&](uint32_t st, int ks, uint32_t f[4][4]) {
        const uint32_t ch0 = ((uint32_t)(2 * ks) ^ (uint32_t)gid) * 16 + tig * 4;
        const uint32_t ch1 = ((uint32_t)(2 * ks + 1) ^ (uint32_t)gid) * 16 + tig * 4;
        #pragma unroll
        for (int mi = 0; mi < 4; mi++) {
            const uint32_t rb = st + (wm + mi * 16 + gid) * 128;
            f[mi][0] = lds32(rb + ch0);
            f[mi][1] = lds32(rb + 8 * 128 + ch0);
            f[mi][2] = lds32(rb + ch1);
            f[mi][3] = lds32(rb + 8 * 128 + ch1);
        }
    };
    auto lfB = [&](uint32_t stb, int ks, uint32_t f[NI][2]) {
        if (BT) {
            const uint32_t ch0 = ((uint32_t)(2 * ks) ^ (uint32_t)gid) * 16 + tig * 4;
            const uint32_t ch1 = ((uint32_t)(2 * ks + 1) ^ (uint32_t)gid) * 16 + tig * 4;
            #pragma unroll
            for (int ni = 0; ni < NI; ni++) {
                const uint32_t rb = stb + (wn + ni * 8 + gid) * 128;
                f[ni][0] = lds32(rb + ch0);
                f[ni][1] = lds32(rb + ch1);
            }
        } else {
            const uint32_t rb = stb + (8 * ks + tig) * (BNN_LD * 4) + (wn + gid) * 4;
            #pragma unroll
            for (int ni = 0; ni < NI; ni++) {
                f[ni][0] = lds32(rb + ni * 32);
                f[ni][1] = lds32(rb + 4 * (BNN_LD * 4) + ni * 32);
            }
        }
    };

    for (int kt = 0; kt < NK; kt++) {
        cp_wait1();                       // stage kt landed
        __syncthreads();                  // stage kt-1 fully consumed by all warps

        const uint32_t st  = sb + (kt % STG) * STGB;
        const uint32_t stb = st + A_BY;

        lfA(st, 0, af[0]); lfB(stb, 0, bf[0]);   // frag buffer 0 first (critical path)
        if (kt + 2 < NK) loads(kt + 2);          // then prefetch into (kt-1)%3
        else cp_commit();                        // keep group accounting uniform

        #pragma unroll
        for (int ks = 0; ks < 4; ks++) {
            const int cur = ks & 1, nxt = cur ^ 1;
            if (ks < 3) { lfA(st, ks + 1, af[nxt]); lfB(stb, ks + 1, bf[nxt]); }
            #pragma unroll
            for (int mi = 0; mi < 4; mi++)
                #pragma unroll
                for (int ni = 0; ni < NI; ni++)
                    mma8(acc[mi][ni], af[cur][mi], bf[cur][ni]);
        }
    }

    // ---- epilogue: bias + scale + optional tf32 round, float2 stores ----
    #pragma unroll
    for (int mi = 0; mi < 4; mi++) {
        const int r = m0 + wm + mi * 16 + gid;
        #pragma unroll
        for (int ni = 0; ni < NI; ni++) {
            const int c = n0 + wn + ni * 8 + tig * 2;
            float b0 = 0.f, b1 = 0.f;
            if (bias) { b0 = bias[c]; b1 = bias[c + 1]; }
            float v0 = (acc[mi][ni][0] + b0) * scale;
            float v1 = (acc[mi][ni][1] + b1) * scale;
            float v2 = (acc[mi][ni][2] + b0) * scale;
            float v3 = (acc[mi][ni][3] + b1) * scale;
            if (round_out) { v0 = tf32r(v0); v1 = tf32r(v1); v2 = tf32r(v2); v3 = tf32r(v3); }
            *(float2*)(Cb + (long long)r * ldc + c)       = make_float2(v0, v1);
            *(float2*)(Cb + (long long)(r + 8) * ldc + c) = make_float2(v2, v3);
        }
    }
}

constexpr int SM_TN256 = STG * (A_BY + 256 * 128);          // 147456
constexpr int SM_NN128 = STG * (A_BY + BK * (128 + 8) * 4); // 101376

// ---------------------------------------------------------------------------
// Fused tf32 rounding of seq + Wq + Wk + Wv (single launch)
// ---------------------------------------------------------------------------
__global__ void __launch_bounds__(256)
round_all(const float4* __restrict__ seq, const float4* __restrict__ wq,
          const float4* __restrict__ wk,  const float4* __restrict__ wv,
          float4* __restrict__ sr, float4* __restrict__ wr)
{
    constexpr int NSEQ = MTOT * D_MODEL / 4;     // 4194304
    constexpr int NW   = FF * D_MODEL / 4;       // 262144
    constexpr int TOT  = NSEQ + 3 * NW;
    for (int i = blockIdx.x * 256 + threadIdx.x; i < TOT; i += gridDim.x * 256) {
        float4 v;
        float4* dst;
        if (i < NSEQ) { v = seq[i]; dst = sr + i; }
        else {
            int j = i - NSEQ, w = j / NW, o = j - w * NW;
            v = (w == 0) ? wq[o] : (w == 1) ? wk[o] : wv[o];
            dst = wr + j;
        }
        v.x = tf32r(v.x); v.y = tf32r(v.y); v.z = tf32r(v.z); v.w = tf32r(v.w);
        *dst = v;
    }
}

// ---------------------------------------------------------------------------
// Row softmax over 2048 cols; output tf32-rounded (feeds PV GEMM).
// ---------------------------------------------------------------------------
__global__ void __launch_bounds__(256)
softmax_tf32(float* __restrict__ S)
{
    __shared__ float red[8];
    float* row = S + (long long)blockIdx.x * SEQ;
    const int tid = threadIdx.x;

    float4 a = ((float4*)row)[tid];
    float4 b = ((float4*)row)[tid + 256];

    float m = fmaxf(fmaxf(fmaxf(a.x, a.y), fmaxf(a.z, a.w)),
                    fmaxf(fmaxf(b.x, b.y), fmaxf(b.z, b.w)));
    #pragma unroll
    for (int o = 16; o > 0; o >>= 1) m = fmaxf(m, __shfl_xor_sync(0xffffffffu, m, o));
    if ((tid & 31) == 0) red[tid >> 5] = m;
    __syncthreads();
    m = red[0];
    #pragma unroll
    for (int i = 1; i < 8; i++) m = fmaxf(m, red[i]);
    __syncthreads();

    a.x = __expf(a.x - m); a.y = __expf(a.y - m); a.z = __expf(a.z - m); a.w = __expf(a.w - m);
    b.x = __expf(b.x - m); b.y = __expf(b.y - m); b.z = __expf(b.z - m); b.w = __expf(b.w - m);
    float s = a.x + a.y + a.z + a.w + b.x + b.y + b.z + b.w;
    #pragma unroll
    for (int o = 16; o > 0; o >>= 1) s += __shfl_xor_sync(0xffffffffu, s, o);
    if ((tid & 31) == 0) red[tid >> 5] = s;
    __syncthreads();
    s = red[0] + red[1] + red[2] + red[3] + red[4] + red[5] + red[6] + red[7];
    const float inv = 1.0f / s;

    a.x = tf32r(a.x * inv); a.y = tf32r(a.y * inv); a.z = tf32r(a.z * inv); a.w = tf32r(a.w * inv);
    b.x = tf32r(b.x * inv); b.y = tf32r(b.y * inv); b.z = tf32r(b.z * inv); b.w = tf32r(b.w * inv);
    ((float4*)row)[tid]       = a;
    ((float4*)row)[tid + 256] = b;
}

// ---------------------------------------------------------------------------
// kernel_launch — graph-capturable, allocation-free.
// Inputs: 0=sequence, 1=Wq, 2=bq, 3=Wk, 4=bk, 5=Wv, 6=bv. Output fp32.
// ---------------------------------------------------------------------------
extern "C" void kernel_launch(void* const* d_in, const int* in_sizes, int n_in,
                              void* d_out, int out_size)
{
    const float* seq = (const float*)d_in[0];
    const float* Wq  = (const float*)d_in[1];
    const float* bq  = (const float*)d_in[2];
    const float* Wk  = (const float*)d_in[3];
    const float* bk  = (const float*)d_in[4];
    const float* Wv  = (const float*)d_in[5];
    const float* bv  = (const float*)d_in[6];
    float* out = (float*)d_out;

    float *SR, *WR, *Qp, *Kp, *Vp, *Sp;
    cudaGetSymbolAddress((void**)&SR, g_SR);
    cudaGetSymbolAddress((void**)&WR, g_WR);
    cudaGetSymbolAddress((void**)&Qp, g_Q);
    cudaGetSymbolAddress((void**)&Kp, g_K);
    cudaGetSymbolAddress((void**)&Vp, g_V);
    cudaGetSymbolAddress((void**)&Sp, g_S);

    cudaFuncSetAttribute(gemm3<true, 256>,  cudaFuncAttributeMaxDynamicSharedMemorySize, SM_TN256);
    cudaFuncSetAttribute(gemm3<false, 128>, cudaFuncAttributeMaxDynamicSharedMemorySize, SM_NN128);

    const dim3 blk(256);
    const size_t WSZ = (size_t)FF * D_MODEL;

    // 0) fused tf32 rounding of all inputs
    round_all<<<2048, blk>>>((const float4*)seq, (const float4*)Wq,
                             (const float4*)Wk, (const float4*)Wv,
                             (float4*)SR, (float4*)WR);

    // 1) fused QKV projections: z selects {W, bias, out, scale}; grid (4,128,3)
    {
        Sel s;
        s.p[0] = { WR + 0 * WSZ, bq, Qp, ATTN_SCALE };
        s.p[1] = { WR + 1 * WSZ, bk, Kp, 1.0f };
        s.p[2] = { WR + 2 * WSZ, bv, Vp, 1.0f };
        const dim3 gp(FF / 256, MTOT / BM, 3);
        gemm3<true, 256><<<gp, blk, SM_TN256>>>(SR, s, 1, D_MODEL, D_MODEL, FF,
                                                0, 0, 0, 1);
    }

    const long long sQK = (long long)SEQ * FF;
    const long long sS  = (long long)SEQ * SEQ;

    // 2) scores: per batch [2048,2048] = Q @ K^T; grid (8,16,8)
    {
        Sel s; s.p[0] = { Kp, nullptr, Sp, 1.0f };
        const dim3 gs(SEQ / 256, SEQ / BM, NB);
        gemm3<true, 256><<<gs, blk, SM_TN256>>>(Qp, s, 0, FF, FF, SEQ,
                                                sQK, sQK, sS, 0);
    }

    // 3) softmax (rounds P to tf32)
    softmax_tf32<<<MTOT, blk>>>(Sp);

    // 4) output: per batch [2048,1024] = P @ V; grid (8,16,8) @ BN=128
    {
        Sel s; s.p[0] = { Vp, nullptr, out, 1.0f };
        const dim3 go(FF / 128, SEQ / BM, NB);
        gemm3<false, 128><<<go, blk, SM_NN128>>>(Sp, s, 0, SEQ, FF, FF,
                                                 sS, sQK, sQK, 0);
    }
}

// round 9
// speedup vs baseline: 1.5887x; 1.0776x over previous
#include <cuda_runtime.h>
#include <cstdint>

#define D_MODEL 1024
#define FF      1024
#define NB      8
#define SEQ     2048
#define MTOT    (NB * SEQ)            // 16384
#define ATTN_SCALE 0.03125f

// ---------------------------------------------------------------------------
// Scratch (device globals: allocation-free)
// ---------------------------------------------------------------------------
__device__ float g_SR[(size_t)MTOT * D_MODEL];       // 64 MiB  seq, tf32-rounded
__device__ float g_WR[(size_t)3 * FF * D_MODEL];     // 12 MiB  Wq/Wk/Wv rounded
__device__ float g_Q [(size_t)MTOT * FF];            // 64 MiB
__device__ float g_K [(size_t)MTOT * FF];            // 64 MiB
__device__ float g_V [(size_t)MTOT * FF];            // 64 MiB
__device__ float g_S [(size_t)NB * SEQ * SEQ];       // 128 MiB

// ---------------------------------------------------------------------------
// Helpers
// ---------------------------------------------------------------------------
__device__ __forceinline__ float tf32r(float x) {
    uint32_t u; asm("cvt.rna.tf32.f32 %0, %1;" : "=r"(u) : "f"(x));
    return __uint_as_float(u);
}
__device__ __forceinline__ uint32_t smem_u32(const void* p) {
    uint32_t a;
    asm("{ .reg .u64 t; cvta.to.shared.u64 t, %1; cvt.u32.u64 %0, t; }" : "=r"(a) : "l"(p));
    return a;
}
__device__ __forceinline__ void cp16(uint32_t dst, const void* src) {
    asm volatile("cp.async.cg.shared.global [%0], [%1], 16;" :: "r"(dst), "l"(src) : "memory");
}
__device__ __forceinline__ void cp_commit() { asm volatile("cp.async.commit_group;" ::: "memory"); }
__device__ __forceinline__ void cp_wait0()  { asm volatile("cp.async.wait_group 0;" ::: "memory"); }
__device__ __forceinline__ uint32_t lds32(uint32_t a) {
    uint32_t v; asm("ld.shared.b32 %0, [%1];" : "=r"(v) : "r"(a));
    return v;
}
__device__ __forceinline__ void mma8(float* c, const uint32_t* a, const uint32_t* b) {
    asm volatile(
        "mma.sync.aligned.m16n8k8.row.col.f32.tf32.tf32.f32 "
        "{%0,%1,%2,%3}, {%4,%5,%6,%7}, {%8,%9}, {%0,%1,%2,%3};\n"
        : "+f"(c[0]), "+f"(c[1]), "+f"(c[2]), "+f"(c[3])
        : "r"(a[0]), "r"(a[1]), "r"(a[2]), "r"(a[3]), "r"(b[0]), "r"(b[1]));
}

// Per-z operand selection (for the fused QKV projection launch)
struct Ptrs { const float* B; const float* bias; float* C; float scale; };
struct Sel  { Ptrs p[3]; };

// ---------------------------------------------------------------------------
// TF32 GEMM v4: C[M,N] = A[M,K]*op(B) (+bias)*scale, optional tf32-round out.
//   BT=true : B[N,K] row-major (C = A B^T)    -- proj, QK^T
//   BT=false: B[K,N] row-major (C = A B)      -- PV
// CTA tile 128 x BNT x 64, 8 warps (warp grid 2x4, warp tile 64 x BNT/4).
// Each stage holds TWO BK=32 sub-tiles (same verified layout/swizzle as v3),
// 2-stage cp.async ring (prefetch distance 1), one barrier per 64-k chunk.
// TN smem: 128B rows, 16B-chunk XOR swizzle. NN B smem: [32][BNT+8] per sub.
// fused=1: blockIdx.z selects sel.p[z] (strides sA/sB/sC are 0 in that mode).
// ---------------------------------------------------------------------------
constexpr int BM = 128, BK = 64, STG = 2;
constexpr int A_SUB = BM * 32 * 4;            // 16384 per sub-tile

template <bool BT, int BNT>
__global__ void __launch_bounds__(256)
gemm4(const float* __restrict__ A, Sel sel, int fused,
      int K, int ldb, int ldc,
      long long sA, long long sB, long long sC,
      int round_out)
{
    constexpr int NI     = BNT / 32;          // n8 blocks per warp
    constexpr int WN     = BNT / 4;           // warp n tile
    constexpr int CPR    = BNT / 4;           // NN 16B-chunks per smem row
    constexpr int BNN_LD = BNT + 8;
    constexpr int B_SUB  = BT ? BNT * 128 : 32 * BNN_LD * 4;
    constexpr int STGB   = 2 * A_SUB + 2 * B_SUB;

    extern __shared__ char smp[];
    const uint32_t sb = smem_u32(smp);
    const int tid = threadIdx.x, lane = tid & 31, warp = tid >> 5;
    const int gid = lane >> 2, tig = lane & 3;
    const int wm = (warp & 1) * 64, wn = (warp >> 1) * WN;
    const int m0 = blockIdx.y * BM, n0 = blockIdx.x * BNT;
    const int z  = blockIdx.z;

    const Ptrs pp = sel.p[fused ? z : 0];
    const float* Ab = A    + (long long)z * sA;
    const float* Bb = pp.B + (long long)z * sB;
    float*       Cb = pp.C + (long long)z * sC;
    const float* bias = pp.bias;
    const float  scale = pp.scale;

    // ---- precomputed cp.async offsets (per thread, 32-bit element offsets) ----
    uint32_t dA[4]; int oA[4];
    #pragma unroll
    for (int i = 0; i < 4; i++) {
        int id = tid + i * 256, r = id >> 3, c = id & 7;
        dA[i] = (uint32_t)(r * 128 + ((c ^ (r & 7)) * 16));
        oA[i] = (m0 + r) * K + c * 4;
    }
    uint32_t dB[NI]; int oB[NI];
    #pragma unroll
    for (int i = 0; i < NI; i++) {
        int id = tid + i * 256;
        if (BT) {
            int r = id >> 3, c = id & 7;
            dB[i] = (uint32_t)(r * 128 + ((c ^ (r & 7)) * 16));
            oB[i] = (n0 + r) * ldb + c * 4;
        } else {
            int kr = id / CPR, c = id % CPR;
            dB[i] = (uint32_t)(kr * (BNN_LD * 4) + c * 16);
            oB[i] = kr * ldb + n0 + c * 4;
        }
    }

    // One stage = two BK=32 sub-tiles: A0 A1 B0 B1
    auto loads = [&](int kt) {                 // kt = 64-wide chunk index
        const uint32_t st = sb + (kt & 1) * STGB;
        #pragma unroll
        for (int s = 0; s < 2; s++) {
            const int kof = kt * BK + s * 32;
            const float* Ak = Ab + kof;
            const uint32_t sa = st + s * A_SUB;
            #pragma unroll
            for (int i = 0; i < 4; i++) cp16(sa + dA[i], Ak + oA[i]);
            const float* Bk = BT ? (Bb + kof) : (Bb + (long long)kof * ldb);
            const uint32_t sbB = st + 2 * A_SUB + s * B_SUB;
            #pragma unroll
            for (int i = 0; i < NI; i++) cp16(sbB + dB[i], Bk + oB[i]);
        }
        cp_commit();
    };

    float acc[4][NI][4];
    #pragma unroll
    for (int i = 0; i < 4; i++)
        #pragma unroll
        for (int j = 0; j < NI; j++)
            #pragma unroll
            for (int l = 0; l < 4; l++) acc[i][j][l] = 0.f;

    const int NK = K / BK;
    loads(0);

    uint32_t af[2][4][4], bf[2][NI][2];

    // ks in 0..7 -> sub-tile ks>>2, k4 = ks&3 within sub
    auto lfA = [&](uint32_t st, int ks, uint32_t f[4][4]) {
        const uint32_t sa = st + (ks >> 2) * A_SUB;
        const int k4 = ks & 3;
        const uint32_t ch0 = ((uint32_t)(2 * k4) ^ (uint32_t)gid) * 16 + tig * 4;
        const uint32_t ch1 = ((uint32_t)(2 * k4 + 1) ^ (uint32_t)gid) * 16 + tig * 4;
        #pragma unroll
        for (int mi = 0; mi < 4; mi++) {
            const uint32_t rb = sa + (wm + mi * 16 + gid) * 128;
            f[mi][0] = lds32(rb + ch0);
            f[mi][1] = lds32(rb + 8 * 128 + ch0);
            f[mi][2] = lds32(rb + ch1);
            f[mi][3] = lds32(rb + 8 * 128 + ch1);
        }
    };
    auto lfB = [&](uint32_t st, int ks, uint32_t f[NI][2]) {
        const uint32_t sbB = st + 2 * A_SUB + (ks >> 2) * B_SUB;
        const int k4 = ks & 3;
        if (BT) {
            const uint32_t ch0 = ((uint32_t)(2 * k4) ^ (uint32_t)gid) * 16 + tig * 4;
            const uint32_t ch1 = ((uint32_t)(2 * k4 + 1) ^ (uint32_t)gid) * 16 + tig * 4;
            #pragma unroll
            for (int ni = 0; ni < NI; ni++) {
                const uint32_t rb = sbB + (wn + ni * 8 + gid) * 128;
                f[ni][0] = lds32(rb + ch0);
                f[ni][1] = lds32(rb + ch1);
            }
        } else {
            const uint32_t rb = sbB + (8 * k4 + tig) * (BNN_LD * 4) + (wn + gid) * 4;
            #pragma unroll
            for (int ni = 0; ni < NI; ni++) {
                f[ni][0] = lds32(rb + ni * 32);
                f[ni][1] = lds32(rb + 4 * (BNN_LD * 4) + ni * 32);
            }
        }
    };

    for (int kt = 0; kt < NK; kt++) {
        cp_wait0();                        // stage kt landed (issued at iter kt-1)
        __syncthreads();                   // all warps done with buffer (kt-1)&1

        const uint32_t st = sb + (kt & 1) * STGB;

        lfA(st, 0, af[0]); lfB(st, 0, bf[0]);   // frag buffer 0 first (critical path)
        if (kt + 1 < NK) loads(kt + 1);         // then prefetch into other buffer

        #pragma unroll
        for (int ks = 0; ks < 8; ks++) {
            const int cur = ks & 1, nxt = cur ^ 1;
            if (ks < 7) { lfA(st, ks + 1, af[nxt]); lfB(st, ks + 1, bf[nxt]); }
            #pragma unroll
            for (int mi = 0; mi < 4; mi++)
                #pragma unroll
                for (int ni = 0; ni < NI; ni++)
                    mma8(acc[mi][ni], af[cur][mi], bf[cur][ni]);
        }
    }

    // ---- epilogue: bias + scale + optional tf32 round, float2 stores ----
    #pragma unroll
    for (int mi = 0; mi < 4; mi++) {
        const int r = m0 + wm + mi * 16 + gid;
        #pragma unroll
        for (int ni = 0; ni < NI; ni++) {
            const int c = n0 + wn + ni * 8 + tig * 2;
            float b0 = 0.f, b1 = 0.f;
            if (bias) { b0 = bias[c]; b1 = bias[c + 1]; }
            float v0 = (acc[mi][ni][0] + b0) * scale;
            float v1 = (acc[mi][ni][1] + b1) * scale;
            float v2 = (acc[mi][ni][2] + b0) * scale;
            float v3 = (acc[mi][ni][3] + b1) * scale;
            if (round_out) { v0 = tf32r(v0); v1 = tf32r(v1); v2 = tf32r(v2); v3 = tf32r(v3); }
            *(float2*)(Cb + (long long)r * ldc + c)       = make_float2(v0, v1);
            *(float2*)(Cb + (long long)(r + 8) * ldc + c) = make_float2(v2, v3);
        }
    }
}

constexpr int SM_TN256 = STG * (2 * A_SUB + 2 * 256 * 128);          // 196608
constexpr int SM_NN128 = STG * (2 * A_SUB + 2 * 32 * (128 + 8) * 4); // 135168

// ---------------------------------------------------------------------------
// Fused tf32 rounding of seq + Wq + Wk + Wv (single launch)
// ---------------------------------------------------------------------------
__global__ void __launch_bounds__(256)
round_all(const float4* __restrict__ seq, const float4* __restrict__ wq,
          const float4* __restrict__ wk,  const float4* __restrict__ wv,
          float4* __restrict__ sr, float4* __restrict__ wr)
{
    constexpr int NSEQ = MTOT * D_MODEL / 4;     // 4194304
    constexpr int NW   = FF * D_MODEL / 4;       // 262144
    constexpr int TOT  = NSEQ + 3 * NW;
    for (int i = blockIdx.x * 256 + threadIdx.x; i < TOT; i += gridDim.x * 256) {
        float4 v;
        float4* dst;
        if (i < NSEQ) { v = seq[i]; dst = sr + i; }
        else {
            int j = i - NSEQ, w = j / NW, o = j - w * NW;
            v = (w == 0) ? wq[o] : (w == 1) ? wk[o] : wv[o];
            dst = wr + j;
        }
        v.x = tf32r(v.x); v.y = tf32r(v.y); v.z = tf32r(v.z); v.w = tf32r(v.w);
        *dst = v;
    }
}

// ---------------------------------------------------------------------------
// Row softmax over 2048 cols; output tf32-rounded (feeds PV GEMM).
// ---------------------------------------------------------------------------
__global__ void __launch_bounds__(256)
softmax_tf32(float* __restrict__ S)
{
    __shared__ float red[8];
    float* row = S + (long long)blockIdx.x * SEQ;
    const int tid = threadIdx.x;

    float4 a = ((float4*)row)[tid];
    float4 b = ((float4*)row)[tid + 256];

    float m = fmaxf(fmaxf(fmaxf(a.x, a.y), fmaxf(a.z, a.w)),
                    fmaxf(fmaxf(b.x, b.y), fmaxf(b.z, b.w)));
    #pragma unroll
    for (int o = 16; o > 0; o >>= 1) m = fmaxf(m, __shfl_xor_sync(0xffffffffu, m, o));
    if ((tid & 31) == 0) red[tid >> 5] = m;
    __syncthreads();
    m = red[0];
    #pragma unroll
    for (int i = 1; i < 8; i++) m = fmaxf(m, red[i]);
    __syncthreads();

    a.x = __expf(a.x - m); a.y = __expf(a.y - m); a.z = __expf(a.z - m); a.w = __expf(a.w - m);
    b.x = __expf(b.x - m); b.y = __expf(b.y - m); b.z = __expf(b.z - m); b.w = __expf(b.w - m);
    float s = a.x + a.y + a.z + a.w + b.x + b.y + b.z + b.w;
    #pragma unroll
    for (int o = 16; o > 0; o >>= 1) s += __shfl_xor_sync(0xffffffffu, s, o);
    if ((tid & 31) == 0) red[tid >> 5] = s;
    __syncthreads();
    s = red[0] + red[1] + red[2] + red[3] + red[4] + red[5] + red[6] + red[7];
    const float inv = 1.0f / s;

    a.x = tf32r(a.x * inv); a.y = tf32r(a.y * inv); a.z = tf32r(a.z * inv); a.w = tf32r(a.w * inv);
    b.x = tf32r(b.x * inv); b.y = tf32r(b.y * inv); b.z = tf32r(b.z * inv); b.w = tf32r(b.w * inv);
    ((float4*)row)[tid]       = a;
    ((float4*)row)[tid + 256] = b;
}

// ---------------------------------------------------------------------------
// kernel_launch — graph-capturable, allocation-free.
// Inputs: 0=sequence, 1=Wq, 2=bq, 3=Wk, 4=bk, 5=Wv, 6=bv. Output fp32.
// ---------------------------------------------------------------------------
extern "C" void kernel_launch(void* const* d_in, const int* in_sizes, int n_in,
                              void* d_out, int out_size)
{
    const float* seq = (const float*)d_in[0];
    const float* Wq  = (const float*)d_in[1];
    const float* bq  = (const float*)d_in[2];
    const float* Wk  = (const float*)d_in[3];
    const float* bk  = (const float*)d_in[4];
    const float* Wv  = (const float*)d_in[5];
    const float* bv  = (const float*)d_in[6];
    float* out = (float*)d_out;

    float *SR, *WR, *Qp, *Kp, *Vp, *Sp;
    cudaGetSymbolAddress((void**)&SR, g_SR);
    cudaGetSymbolAddress((void**)&WR, g_WR);
    cudaGetSymbolAddress((void**)&Qp, g_Q);
    cudaGetSymbolAddress((void**)&Kp, g_K);
    cudaGetSymbolAddress((void**)&Vp, g_V);
    cudaGetSymbolAddress((void**)&Sp, g_S);

    cudaFuncSetAttribute(gemm4<true, 256>,  cudaFuncAttributeMaxDynamicSharedMemorySize, SM_TN256);
    cudaFuncSetAttribute(gemm4<false, 128>, cudaFuncAttributeMaxDynamicSharedMemorySize, SM_NN128);

    const dim3 blk(256);
    const size_t WSZ = (size_t)FF * D_MODEL;

    // 0) fused tf32 rounding of all inputs
    round_all<<<2048, blk>>>((const float4*)seq, (const float4*)Wq,
                             (const float4*)Wk, (const float4*)Wv,
                             (float4*)SR, (float4*)WR);

    // 1) fused QKV projections: z selects {W, bias, out, scale}; grid (4,128,3)
    {
        Sel s;
        s.p[0] = { WR + 0 * WSZ, bq, Qp, ATTN_SCALE };
        s.p[1] = { WR + 1 * WSZ, bk, Kp, 1.0f };
        s.p[2] = { WR + 2 * WSZ, bv, Vp, 1.0f };
        const dim3 gp(FF / 256, MTOT / BM, 3);
        gemm4<true, 256><<<gp, blk, SM_TN256>>>(SR, s, 1, D_MODEL, D_MODEL, FF,
                                                0, 0, 0, 1);
    }

    const long long sQK = (long long)SEQ * FF;
    const long long sS  = (long long)SEQ * SEQ;

    // 2) scores: per batch [2048,2048] = Q @ K^T; grid (8,16,8)
    {
        Sel s; s.p[0] = { Kp, nullptr, Sp, 1.0f };
        const dim3 gs(SEQ / 256, SEQ / BM, NB);
        gemm4<true, 256><<<gs, blk, SM_TN256>>>(Qp, s, 0, FF, FF, SEQ,
                                                sQK, sQK, sS, 0);
    }

    // 3) softmax (rounds P to tf32)
    softmax_tf32<<<MTOT, blk>>>(Sp);

    // 4) output: per batch [2048,1024] = P @ V; grid (8,16,8) @ BN=128
    {
        Sel s; s.p[0] = { Vp, nullptr, out, 1.0f };
        const dim3 go(FF / 128, SEQ / BM, NB);
        gemm4<false, 128><<<go, blk, SM_NN128>>>(Sp, s, 0, SEQ, FF, FF,
                                                 sS, sQK, sQK, 0);
    }
}